// round 3
// baseline (speedup 1.0000x reference)
#include <cuda_runtime.h>

#define B_ 4
#define L_ 2048
#define H_ 16
#define DH_ 64
#define DM_ 1024
#define N3_ 3072
#define BH_ (B_*H_)
#define OUT_ELEMS_ (B_*L_*DM_)   // 8388608

// Scratch (device globals: allocation-free per harness rules)
__device__ float g_q[BH_*L_*DH_];
__device__ float g_k[BH_*L_*DH_];
__device__ float g_v[BH_*L_*DH_];
__device__ float g_hout[B_*L_*DM_];
__device__ float g_rowsum[BH_*L_];

// ---------------------------------------------------------------------------
// QKV GEMM: X[8192,1024] @ W[1024,3072] + bias, scattered into q/k/v
// laid out [bh][l][dh]. Tiles: BM=BN=128, BK=16, 256 threads, 8x8 microtile.
// ---------------------------------------------------------------------------
__global__ __launch_bounds__(256) void qkv_gemm_kernel(
    const float* __restrict__ X, const float* __restrict__ W,
    const float* __restrict__ bias)
{
    __shared__ float sA[16][132];
    __shared__ float sB[16][132];
    const int tid = threadIdx.x;
    const int tx = tid & 15, ty = tid >> 4;
    const int m0 = blockIdx.y * 128;
    const int n0 = blockIdx.x * 128;

    float acc[8][8];
#pragma unroll
    for (int i = 0; i < 8; i++)
#pragma unroll
        for (int j = 0; j < 8; j++) acc[i][j] = 0.f;

    const int arow = tid >> 1;          // 0..127
    const int ak0  = (tid & 1) * 8;     // 0 / 8
    const int brow = tid >> 4;          // 0..15
    const int bc0  = (tid & 15) * 8;    // 0..120

    for (int k0 = 0; k0 < DM_; k0 += 16) {
        float4 a0 = *(const float4*)(X + (size_t)(m0 + arow) * DM_ + k0 + ak0);
        float4 a1 = *(const float4*)(X + (size_t)(m0 + arow) * DM_ + k0 + ak0 + 4);
        sA[ak0 + 0][arow] = a0.x; sA[ak0 + 1][arow] = a0.y;
        sA[ak0 + 2][arow] = a0.z; sA[ak0 + 3][arow] = a0.w;
        sA[ak0 + 4][arow] = a1.x; sA[ak0 + 5][arow] = a1.y;
        sA[ak0 + 6][arow] = a1.z; sA[ak0 + 7][arow] = a1.w;
        *(float4*)&sB[brow][bc0]     = *(const float4*)(W + (size_t)(k0 + brow) * N3_ + n0 + bc0);
        *(float4*)&sB[brow][bc0 + 4] = *(const float4*)(W + (size_t)(k0 + brow) * N3_ + n0 + bc0 + 4);
        __syncthreads();
#pragma unroll
        for (int k = 0; k < 16; k++) {
            float4 a00 = *(const float4*)&sA[k][ty * 8];
            float4 a01 = *(const float4*)&sA[k][ty * 8 + 4];
            float4 b00 = *(const float4*)&sB[k][tx * 8];
            float4 b01 = *(const float4*)&sB[k][tx * 8 + 4];
            float ar[8] = {a00.x, a00.y, a00.z, a00.w, a01.x, a01.y, a01.z, a01.w};
            float br[8] = {b00.x, b00.y, b00.z, b00.w, b01.x, b01.y, b01.z, b01.w};
#pragma unroll
            for (int i = 0; i < 8; i++)
#pragma unroll
                for (int j = 0; j < 8; j++) acc[i][j] += ar[i] * br[j];
        }
        __syncthreads();
    }

    // Epilogue: bias + scatter. Each row of 8 outputs stays inside one
    // (matrix, head) because n-tile granularity 8 divides head width 64.
#pragma unroll
    for (int i = 0; i < 8; i++) {
        int m = m0 + ty * 8 + i;
        int bidx = m >> 11;            // m / 2048
        int l = m & 2047;
        int nb = n0 + tx * 8;
        int mat = nb >> 10;
        int cc = nb & 1023;
        int h = cc >> 6;
        int d0 = cc & 63;
        float* dst = (mat == 0) ? g_q : (mat == 1) ? g_k : g_v;
        float* p = dst + (((size_t)(bidx * H_ + h)) * L_ + l) * DH_ + d0;
        float4 v0, v1;
        v0.x = acc[i][0] + bias[nb + 0];
        v0.y = acc[i][1] + bias[nb + 1];
        v0.z = acc[i][2] + bias[nb + 2];
        v0.w = acc[i][3] + bias[nb + 3];
        v1.x = acc[i][4] + bias[nb + 4];
        v1.y = acc[i][5] + bias[nb + 5];
        v1.z = acc[i][6] + bias[nb + 6];
        v1.w = acc[i][7] + bias[nb + 7];
        *(float4*)p = v0;
        *(float4*)(p + 4) = v1;
    }
}

// ---------------------------------------------------------------------------
// Fused attention: per CTA: 32 q-rows of one (b,h); loop over 64-key tiles.
//  - scores (no max subtraction: |s| <~ 8, exp safe in fp32)
//  - e = exp(s/8): write unnormalized to global attn, keep in smem
//  - acc += e @ V tile; row-sums accumulated in registers
//  - epilogue: hout = acc / rowsum; rowsum stored for the rescale pass
// ---------------------------------------------------------------------------
__global__ __launch_bounds__(256) void attn_kernel(float* __restrict__ attn_out)
{
    __shared__ float sq[32][68];
    __shared__ float sk[64][65];   // K tile; rows 0..31 reused as P tile
    __shared__ float sv[64][68];
    __shared__ float srow[32];

    const int tid = threadIdx.x;
    const int bh = blockIdx.y;
    const int q0 = blockIdx.x * 32;
    const float* Q = g_q + (size_t)bh * L_ * DH_;
    const float* K = g_k + (size_t)bh * L_ * DH_;
    const float* V = g_v + (size_t)bh * L_ * DH_;
    float* attn = attn_out + (size_t)bh * L_ * L_;

    // load q tile (32x64)
    {
        int row = tid >> 3;
        int d0 = (tid & 7) * 8;
        float4 qa = *(const float4*)(Q + (size_t)(q0 + row) * DH_ + d0);
        float4 qb = *(const float4*)(Q + (size_t)(q0 + row) * DH_ + d0 + 4);
        sq[row][d0 + 0] = qa.x; sq[row][d0 + 1] = qa.y;
        sq[row][d0 + 2] = qa.z; sq[row][d0 + 3] = qa.w;
        sq[row][d0 + 4] = qb.x; sq[row][d0 + 5] = qb.y;
        sq[row][d0 + 6] = qb.z; sq[row][d0 + 7] = qb.w;
    }

    const int row2 = tid >> 4;        // 0..15
    const int kc   = tid & 15;        // 0..15
    const int kc4  = kc * 4;
    const int r0 = row2 * 2, r1 = r0 + 1;
    const int arow = tid >> 3;        // 0..31 (AV role)
    const int dg   = tid & 7;         // 0..7  (AV role: dims dg*8..dg*8+7)

    float ssum0 = 0.f, ssum1 = 0.f;
    float acc[8];
#pragma unroll
    for (int j = 0; j < 8; j++) acc[j] = 0.f;

    const int ldrow = tid >> 2;              // 0..63
    const int ldd0  = (tid & 3) * 16;        // 0,16,32,48

    for (int kt = 0; kt < L_ / 64; kt++) {
        const int k0g = kt * 64;
        // load K & V tiles (64x64 each)
#pragma unroll
        for (int jj = 0; jj < 4; jj++) {
            float4 kv = *(const float4*)(K + (size_t)(k0g + ldrow) * DH_ + ldd0 + jj * 4);
            float4 vv = *(const float4*)(V + (size_t)(k0g + ldrow) * DH_ + ldd0 + jj * 4);
            sk[ldrow][ldd0 + jj * 4 + 0] = kv.x;
            sk[ldrow][ldd0 + jj * 4 + 1] = kv.y;
            sk[ldrow][ldd0 + jj * 4 + 2] = kv.z;
            sk[ldrow][ldd0 + jj * 4 + 3] = kv.w;
            *(float4*)&sv[ldrow][ldd0 + jj * 4] = vv;
        }
        __syncthreads();

        // scores: 2 rows x 4 keys per thread
        float sc0[4] = {0.f, 0.f, 0.f, 0.f};
        float sc1[4] = {0.f, 0.f, 0.f, 0.f};
#pragma unroll 16
        for (int d = 0; d < 64; d++) {
            float qa = sq[r0][d];
            float qb = sq[r1][d];
#pragma unroll
            for (int j = 0; j < 4; j++) {
                float kv = sk[kc4 + j][d];
                sc0[j] += qa * kv;
                sc1[j] += qb * kv;
            }
        }

        float e0[4], e1[4];
#pragma unroll
        for (int j = 0; j < 4; j++) {
            e0[j] = __expf(sc0[j] * 0.125f);
            e1[j] = __expf(sc1[j] * 0.125f);
        }
        float ls0 = e0[0] + e0[1] + e0[2] + e0[3];
        float ls1 = e1[0] + e1[1] + e1[2] + e1[3];
#pragma unroll
        for (int off = 1; off < 16; off <<= 1) {
            ls0 += __shfl_xor_sync(0xffffffffu, ls0, off);
            ls1 += __shfl_xor_sync(0xffffffffu, ls1, off);
        }
        ssum0 += ls0;
        ssum1 += ls1;

        // write unnormalized e to global attn
        *(float4*)(attn + (size_t)(q0 + r0) * L_ + k0g + kc4) =
            make_float4(e0[0], e0[1], e0[2], e0[3]);
        *(float4*)(attn + (size_t)(q0 + r1) * L_ + k0g + kc4) =
            make_float4(e1[0], e1[1], e1[2], e1[3]);

        __syncthreads();   // everyone done reading K tile
        // stash P (32x64) in rows 0..31 of sk
#pragma unroll
        for (int j = 0; j < 4; j++) {
            sk[r0][kc4 + j] = e0[j];
            sk[r1][kc4 + j] = e1[j];
        }
        __syncthreads();

        // AV: acc[arow][dg*8 + j] += sum_k P[arow][k] * V[k][dg*8 + j]
#pragma unroll 16
        for (int k = 0; k < 64; k++) {
            float pv = sk[arow][k];
            float4 v0 = *(const float4*)&sv[k][dg * 8];
            float4 v1 = *(const float4*)&sv[k][dg * 8 + 4];
            acc[0] += pv * v0.x; acc[1] += pv * v0.y;
            acc[2] += pv * v0.z; acc[3] += pv * v0.w;
            acc[4] += pv * v1.x; acc[5] += pv * v1.y;
            acc[6] += pv * v1.z; acc[7] += pv * v1.w;
        }
        __syncthreads();
    }

    if (kc == 0) { srow[r0] = ssum0; srow[r1] = ssum1; }
    __syncthreads();

    float inv = 1.f / srow[arow];
    int bidx = bh >> 4;
    int h = bh & 15;
    float* hp = g_hout + ((size_t)(bidx * L_) + q0 + arow) * DM_ + h * DH_ + dg * 8;
    float4 o0, o1;
    o0.x = acc[0] * inv; o0.y = acc[1] * inv; o0.z = acc[2] * inv; o0.w = acc[3] * inv;
    o1.x = acc[4] * inv; o1.y = acc[5] * inv; o1.z = acc[6] * inv; o1.w = acc[7] * inv;
    *(float4*)hp = o0;
    *(float4*)(hp + 4) = o1;
    if (dg == 0) g_rowsum[(size_t)bh * L_ + q0 + arow] = srow[arow];
}

// ---------------------------------------------------------------------------
// Rescale attn rows by 1/rowsum (bandwidth-bound, ~2.1 GB traffic)
// ---------------------------------------------------------------------------
__global__ __launch_bounds__(256) void scale_attn_kernel(float* __restrict__ attn)
{
    size_t row = blockIdx.x;
    float inv = 1.f / g_rowsum[row];
    float4* p = (float4*)(attn + row * L_);
    int tid = threadIdx.x;
#pragma unroll
    for (int i = 0; i < L_ / 4 / 256; i++) {
        float4 v = p[tid + i * 256];
        v.x *= inv; v.y *= inv; v.z *= inv; v.w *= inv;
        p[tid + i * 256] = v;
    }
}

// ---------------------------------------------------------------------------
// Output projection: hout[8192,1024] @ W_out[1024,1024] + b_out -> d_out
// ---------------------------------------------------------------------------
__global__ __launch_bounds__(256) void out_gemm_kernel(
    float* __restrict__ Cout, const float* __restrict__ W,
    const float* __restrict__ bias)
{
    __shared__ float sA[16][132];
    __shared__ float sB[16][132];
    const int tid = threadIdx.x;
    const int tx = tid & 15, ty = tid >> 4;
    const int m0 = blockIdx.y * 128;
    const int n0 = blockIdx.x * 128;

    float acc[8][8];
#pragma unroll
    for (int i = 0; i < 8; i++)
#pragma unroll
        for (int j = 0; j < 8; j++) acc[i][j] = 0.f;

    const int arow = tid >> 1;
    const int ak0  = (tid & 1) * 8;
    const int brow = tid >> 4;
    const int bc0  = (tid & 15) * 8;

    for (int k0 = 0; k0 < DM_; k0 += 16) {
        float4 a0 = *(const float4*)(g_hout + (size_t)(m0 + arow) * DM_ + k0 + ak0);
        float4 a1 = *(const float4*)(g_hout + (size_t)(m0 + arow) * DM_ + k0 + ak0 + 4);
        sA[ak0 + 0][arow] = a0.x; sA[ak0 + 1][arow] = a0.y;
        sA[ak0 + 2][arow] = a0.z; sA[ak0 + 3][arow] = a0.w;
        sA[ak0 + 4][arow] = a1.x; sA[ak0 + 5][arow] = a1.y;
        sA[ak0 + 6][arow] = a1.z; sA[ak0 + 7][arow] = a1.w;
        *(float4*)&sB[brow][bc0]     = *(const float4*)(W + (size_t)(k0 + brow) * DM_ + n0 + bc0);
        *(float4*)&sB[brow][bc0 + 4] = *(const float4*)(W + (size_t)(k0 + brow) * DM_ + n0 + bc0 + 4);
        __syncthreads();
#pragma unroll
        for (int k = 0; k < 16; k++) {
            float4 a00 = *(const float4*)&sA[k][ty * 8];
            float4 a01 = *(const float4*)&sA[k][ty * 8 + 4];
            float4 b00 = *(const float4*)&sB[k][tx * 8];
            float4 b01 = *(const float4*)&sB[k][tx * 8 + 4];
            float ar[8] = {a00.x, a00.y, a00.z, a00.w, a01.x, a01.y, a01.z, a01.w};
            float br[8] = {b00.x, b00.y, b00.z, b00.w, b01.x, b01.y, b01.z, b01.w};
#pragma unroll
            for (int i = 0; i < 8; i++)
#pragma unroll
                for (int j = 0; j < 8; j++) acc[i][j] += ar[i] * br[j];
        }
        __syncthreads();
    }

#pragma unroll
    for (int i = 0; i < 8; i++) {
        int m = m0 + ty * 8 + i;
        int nb = n0 + tx * 8;
        float* p = Cout + (size_t)m * DM_ + nb;
        float4 v0, v1;
        v0.x = acc[i][0] + bias[nb + 0];
        v0.y = acc[i][1] + bias[nb + 1];
        v0.z = acc[i][2] + bias[nb + 2];
        v0.w = acc[i][3] + bias[nb + 3];
        v1.x = acc[i][4] + bias[nb + 4];
        v1.y = acc[i][5] + bias[nb + 5];
        v1.z = acc[i][6] + bias[nb + 6];
        v1.w = acc[i][7] + bias[nb + 7];
        *(float4*)p = v0;
        *(float4*)(p + 4) = v1;
    }
}

// ---------------------------------------------------------------------------
extern "C" void kernel_launch(void* const* d_in, const int* in_sizes, int n_in,
                              void* d_out, int out_size)
{
    (void)in_sizes; (void)n_in; (void)out_size;
    const float* x    = (const float*)d_in[0];
    const float* Wqkv = (const float*)d_in[1];
    const float* bqkv = (const float*)d_in[2];
    const float* Wout = (const float*)d_in[3];
    const float* bout = (const float*)d_in[4];
    float* out  = (float*)d_out;
    float* attn = out + OUT_ELEMS_;

    qkv_gemm_kernel<<<dim3(N3_ / 128, (B_ * L_) / 128), 256>>>(x, Wqkv, bqkv);
    attn_kernel<<<dim3(L_ / 32, BH_), 256>>>(attn);
    scale_attn_kernel<<<dim3(BH_ * L_), 256>>>(attn);
    out_gemm_kernel<<<dim3(DM_ / 128, (B_ * L_) / 128), 256>>>(out, Wout, bout);
}

// round 4
// speedup vs baseline: 2.3190x; 2.3190x over previous
#include <cuda_runtime.h>

#define B_ 4
#define L_ 2048
#define H_ 16
#define DH_ 64
#define DM_ 1024
#define N3_ 3072
#define BH_ (B_*H_)
#define OUT_ELEMS_ (B_*L_*DM_)   // 8388608

// Scratch (device globals: allocation-free per harness rules)
__device__ float g_q[BH_*L_*DH_];
__device__ float g_k[BH_*L_*DH_];
__device__ float g_v[BH_*L_*DH_];
__device__ float g_hout[B_*L_*DM_];
__device__ float g_rowsum[BH_*L_];

// ---------------------------------------------------------------------------
// f32x2 packed-FMA helpers (sm_103a FFMA2 — only reachable via PTX)
// ---------------------------------------------------------------------------
__device__ __forceinline__ unsigned long long pk2(float x, float y) {
    unsigned long long r;
    asm("mov.b64 %0, {%1, %2};" : "=l"(r) : "f"(x), "f"(y));
    return r;
}
__device__ __forceinline__ float2 upk2(unsigned long long v) {
    float lo, hi;
    asm("mov.b64 {%0, %1}, %2;" : "=f"(lo), "=f"(hi) : "l"(v));
    return make_float2(lo, hi);
}
__device__ __forceinline__ void fma2(unsigned long long& d,
                                     unsigned long long a,
                                     unsigned long long b) {
    asm("fma.rn.f32x2 %0, %1, %2, %3;" : "=l"(d) : "l"(a), "l"(b), "l"(d));
}

// ---------------------------------------------------------------------------
// QKV GEMM: X[8192,1024] @ W[1024,3072] + bias, scattered into q/k/v
// [bh][l][dh]. BM=BN=128, BK=16, 256 threads, 8x8 microtile, FFMA2 mainloop.
// ---------------------------------------------------------------------------
__device__ __forceinline__ void scatter_qkv_row(int m, int nb, const float* v,
                                                const float* __restrict__ bias) {
    int bidx = m >> 11;            // m / 2048
    int l = m & 2047;
    int mat = nb >> 10;
    int cc = nb & 1023;
    int h = cc >> 6;
    int d0 = cc & 63;
    float* dst = (mat == 0) ? g_q : (mat == 1) ? g_k : g_v;
    float* p = dst + (((size_t)(bidx * H_ + h)) * L_ + l) * DH_ + d0;
    float4 a, b;
    a.x = v[0] + bias[nb + 0]; a.y = v[1] + bias[nb + 1];
    a.z = v[2] + bias[nb + 2]; a.w = v[3] + bias[nb + 3];
    b.x = v[4] + bias[nb + 4]; b.y = v[5] + bias[nb + 5];
    b.z = v[6] + bias[nb + 6]; b.w = v[7] + bias[nb + 7];
    *(float4*)p = a;
    *(float4*)(p + 4) = b;
}

__global__ __launch_bounds__(256) void qkv_gemm_kernel(
    const float* __restrict__ X, const float* __restrict__ W,
    const float* __restrict__ bias)
{
    __shared__ float sA[16][132];
    __shared__ float sB[16][132];
    const int tid = threadIdx.x;
    const int tx = tid & 15, ty = tid >> 4;
    const int m0 = blockIdx.y * 128;
    const int n0 = blockIdx.x * 128;

    unsigned long long acc[4][8];
#pragma unroll
    for (int p = 0; p < 4; p++)
#pragma unroll
        for (int j = 0; j < 8; j++) acc[p][j] = 0ull;

    const int arow = tid >> 1;          // 0..127
    const int ak0  = (tid & 1) * 8;     // 0 / 8
    const int brow = tid >> 4;          // 0..15
    const int bc0  = (tid & 15) * 8;    // 0..120

    for (int k0 = 0; k0 < DM_; k0 += 16) {
        float4 a0 = *(const float4*)(X + (size_t)(m0 + arow) * DM_ + k0 + ak0);
        float4 a1 = *(const float4*)(X + (size_t)(m0 + arow) * DM_ + k0 + ak0 + 4);
        sA[ak0 + 0][arow] = a0.x; sA[ak0 + 1][arow] = a0.y;
        sA[ak0 + 2][arow] = a0.z; sA[ak0 + 3][arow] = a0.w;
        sA[ak0 + 4][arow] = a1.x; sA[ak0 + 5][arow] = a1.y;
        sA[ak0 + 6][arow] = a1.z; sA[ak0 + 7][arow] = a1.w;
        *(float4*)&sB[brow][bc0]     = *(const float4*)(W + (size_t)(k0 + brow) * N3_ + n0 + bc0);
        *(float4*)&sB[brow][bc0 + 4] = *(const float4*)(W + (size_t)(k0 + brow) * N3_ + n0 + bc0 + 4);
        __syncthreads();
#pragma unroll
        for (int k = 0; k < 16; k++) {
            ulonglong2 aA = *(const ulonglong2*)&sA[k][ty * 8];
            ulonglong2 aB = *(const ulonglong2*)&sA[k][ty * 8 + 4];
            float4 b0 = *(const float4*)&sB[k][tx * 8];
            float4 b1 = *(const float4*)&sB[k][tx * 8 + 4];
            float bj[8] = {b0.x, b0.y, b0.z, b0.w, b1.x, b1.y, b1.z, b1.w};
#pragma unroll
            for (int j = 0; j < 8; j++) {
                unsigned long long bb = pk2(bj[j], bj[j]);
                fma2(acc[0][j], aA.x, bb);
                fma2(acc[1][j], aA.y, bb);
                fma2(acc[2][j], aB.x, bb);
                fma2(acc[3][j], aB.y, bb);
            }
        }
        __syncthreads();
    }

#pragma unroll
    for (int p = 0; p < 4; p++) {
        float2 u[8];
#pragma unroll
        for (int j = 0; j < 8; j++) u[j] = upk2(acc[p][j]);
        float v0[8], v1[8];
#pragma unroll
        for (int j = 0; j < 8; j++) { v0[j] = u[j].x; v1[j] = u[j].y; }
        int nb = n0 + tx * 8;
        scatter_qkv_row(m0 + ty * 8 + 2 * p,     nb, v0, bias);
        scatter_qkv_row(m0 + ty * 8 + 2 * p + 1, nb, v1, bias);
    }
}

// ---------------------------------------------------------------------------
// Fused attention: per CTA: 128 q-rows of one (b,h); loop over 64-key tiles.
// Transposed Q/K tiles in smem, FFMA2 score loop (q row-pairs packed, k
// broadcast). Unnormalized e written to global attn; the AV pass reads the
// just-written tile back through L1 (same-CTA STG->syncthreads->LDG),
// avoiding a 64KB smem P buffer. Rowsums kept in registers; final normalize
// of hout here, attn rescaled in a later bandwidth pass.
// ---------------------------------------------------------------------------
// dyn smem layout (floats):
//  sqT [64][132] at 0       (d-major, 128 q rows)   8448
//  skT [64][68]  at 8448    (d-major, 64 keys)      4352
//  sv  [64][68]  at 12800   (k-major, 64 dims)      4352
//  srow[128]     at 17152                            128
#define ATTN_SMEM_FLOATS 17280
#define ATTN_SMEM_BYTES  (ATTN_SMEM_FLOATS * 4)

__global__ __launch_bounds__(256, 2) void attn_kernel(float* __restrict__ attn_out)
{
    extern __shared__ float sm[];
    float* sqT = sm;            // [d][row] stride 132
    float* skT = sm + 8448;     // [d][key] stride 68
    float* sv  = sm + 12800;    // [k][dim] stride 68
    float* srow = sm + 17152;   // [128]

    const int tid = threadIdx.x;
    const int bh = blockIdx.y;
    const int q0 = blockIdx.x * 128;
    const float* Q = g_q + (size_t)bh * L_ * DH_;
    const float* K = g_k + (size_t)bh * L_ * DH_;
    const float* V = g_v + (size_t)bh * L_ * DH_;
    float* attn = attn_out + (size_t)bh * L_ * L_;

    // load Q tile transposed: sqT[d][row]
    {
        int lr = tid >> 1;
        int c0 = (tid & 1) * 32;
#pragma unroll
        for (int w = 0; w < 8; w++) {
            float4 qv = *(const float4*)(Q + (size_t)(q0 + lr) * DH_ + c0 + w * 4);
            sqT[(c0 + w * 4 + 0) * 132 + lr] = qv.x;
            sqT[(c0 + w * 4 + 1) * 132 + lr] = qv.y;
            sqT[(c0 + w * 4 + 2) * 132 + lr] = qv.z;
            sqT[(c0 + w * 4 + 3) * 132 + lr] = qv.w;
        }
    }

    const int ty = tid >> 4;   // 0..15: rows ty*8 .. ty*8+7
    const int tx = tid & 15;   // 0..15: keys/dims tx*4 .. tx*4+3

    unsigned long long oacc[8][2];     // AV accum: [row i][dim-pair], dims tx*4..+3
#pragma unroll
    for (int i = 0; i < 8; i++) { oacc[i][0] = 0ull; oacc[i][1] = 0ull; }
    float rsum[8];
#pragma unroll
    for (int i = 0; i < 8; i++) rsum[i] = 0.f;

    const int klr = tid >> 2;   // 0..63: key row for loads
    const int kc  = tid & 3;

    for (int kt = 0; kt < L_ / 64; kt++) {
        const int k0g = kt * 64;
        // load K transposed + V row-major
#pragma unroll
        for (int jj = 0; jj < 4; jj++) {
            int d0 = kc * 4 + jj * 16;
            float4 kv = *(const float4*)(K + (size_t)(k0g + klr) * DH_ + d0);
            skT[(d0 + 0) * 68 + klr] = kv.x;
            skT[(d0 + 1) * 68 + klr] = kv.y;
            skT[(d0 + 2) * 68 + klr] = kv.z;
            skT[(d0 + 3) * 68 + klr] = kv.w;
            int vd = kc * 16 + jj * 4;
            float4 vv = *(const float4*)(V + (size_t)(k0g + klr) * DH_ + vd);
            *(float4*)&sv[klr * 68 + vd] = vv;
        }
        __syncthreads();

        // scores: rows ty*8..+7 (4 f32x2 row-pairs), keys tx*4..+3
        unsigned long long s[4][4];
#pragma unroll
        for (int p = 0; p < 4; p++)
#pragma unroll
            for (int j = 0; j < 4; j++) s[p][j] = 0ull;

#pragma unroll 4
        for (int d = 0; d < 64; d++) {
            ulonglong2 qa = *(const ulonglong2*)&sqT[d * 132 + ty * 8];
            ulonglong2 qb = *(const ulonglong2*)&sqT[d * 132 + ty * 8 + 4];
            float4 kf = *(const float4*)&skT[d * 68 + tx * 4];
            float kj[4] = {kf.x, kf.y, kf.z, kf.w};
#pragma unroll
            for (int j = 0; j < 4; j++) {
                unsigned long long kk = pk2(kj[j], kj[j]);
                fma2(s[0][j], qa.x, kk);
                fma2(s[1][j], qa.y, kk);
                fma2(s[2][j], qb.x, kk);
                fma2(s[3][j], qb.y, kk);
            }
        }

        // exp + rowsum partials + write unnormalized e to global attn
        float ev[8][4];
#pragma unroll
        for (int p = 0; p < 4; p++)
#pragma unroll
            for (int j = 0; j < 4; j++) {
                float2 u = upk2(s[p][j]);
                ev[2 * p + 0][j] = __expf(u.x * 0.125f);
                ev[2 * p + 1][j] = __expf(u.y * 0.125f);
            }
#pragma unroll
        for (int i = 0; i < 8; i++) {
            float ls = ev[i][0] + ev[i][1] + ev[i][2] + ev[i][3];
#pragma unroll
            for (int off = 1; off < 16; off <<= 1)
                ls += __shfl_xor_sync(0xffffffffu, ls, off);
            rsum[i] += ls;
            *(float4*)(attn + (size_t)(q0 + ty * 8 + i) * L_ + k0g + tx * 4) =
                make_float4(ev[i][0], ev[i][1], ev[i][2], ev[i][3]);
        }

        __syncthreads();   // attn tile writes visible CTA-wide; scores done with skT

        // AV: rows ty*8..+7, dims tx*4..+3; P read back from global (L1 hit)
#pragma unroll 2
        for (int k = 0; k < 64; k += 4) {
            float4 pr[8];
#pragma unroll
            for (int i = 0; i < 8; i++)
                pr[i] = *(const float4*)(attn + (size_t)(q0 + ty * 8 + i) * L_ + k0g + k);
#pragma unroll
            for (int t = 0; t < 4; t++) {
                ulonglong2 vt = *(const ulonglong2*)&sv[(k + t) * 68 + tx * 4];
#pragma unroll
                for (int i = 0; i < 8; i++) {
                    float pv = (t == 0) ? pr[i].x : (t == 1) ? pr[i].y
                             : (t == 2) ? pr[i].z : pr[i].w;
                    unsigned long long pp = pk2(pv, pv);
                    fma2(oacc[i][0], pp, vt.x);
                    fma2(oacc[i][1], pp, vt.y);
                }
            }
        }
        __syncthreads();   // before next tile overwrites skT/sv
    }

    if (tx == 0) {
#pragma unroll
        for (int i = 0; i < 8; i++) srow[ty * 8 + i] = rsum[i];
    }
    __syncthreads();

    const int bidx = bh >> 4;
    const int h = bh & 15;
#pragma unroll
    for (int i = 0; i < 8; i++) {
        float inv = 1.f / srow[ty * 8 + i];
        float2 u0 = upk2(oacc[i][0]);
        float2 u1 = upk2(oacc[i][1]);
        float4 o = make_float4(u0.x * inv, u0.y * inv, u1.x * inv, u1.y * inv);
        *(float4*)(g_hout + ((size_t)(bidx * L_) + q0 + ty * 8 + i) * DM_
                   + h * DH_ + tx * 4) = o;
    }
    if (tid < 128) g_rowsum[(size_t)bh * L_ + q0 + tid] = srow[tid];
}

// ---------------------------------------------------------------------------
// Rescale attn rows by 1/rowsum (bandwidth-bound, ~2.1 GB traffic)
// ---------------------------------------------------------------------------
__global__ __launch_bounds__(256) void scale_attn_kernel(float* __restrict__ attn)
{
    size_t row = blockIdx.x;
    float inv = 1.f / g_rowsum[row];
    float4* p = (float4*)(attn + row * L_);
    int tid = threadIdx.x;
#pragma unroll
    for (int i = 0; i < L_ / 4 / 256; i++) {
        float4 v = p[tid + i * 256];
        v.x *= inv; v.y *= inv; v.z *= inv; v.w *= inv;
        p[tid + i * 256] = v;
    }
}

// ---------------------------------------------------------------------------
// Output projection: hout[8192,1024] @ W_out[1024,1024] + b_out -> d_out
// FFMA2 mainloop, same structure as qkv_gemm.
// ---------------------------------------------------------------------------
__global__ __launch_bounds__(256) void out_gemm_kernel(
    float* __restrict__ Cout, const float* __restrict__ W,
    const float* __restrict__ bias)
{
    __shared__ float sA[16][132];
    __shared__ float sB[16][132];
    const int tid = threadIdx.x;
    const int tx = tid & 15, ty = tid >> 4;
    const int m0 = blockIdx.y * 128;
    const int n0 = blockIdx.x * 128;

    unsigned long long acc[4][8];
#pragma unroll
    for (int p = 0; p < 4; p++)
#pragma unroll
        for (int j = 0; j < 8; j++) acc[p][j] = 0ull;

    const int arow = tid >> 1;
    const int ak0  = (tid & 1) * 8;
    const int brow = tid >> 4;
    const int bc0  = (tid & 15) * 8;

    for (int k0 = 0; k0 < DM_; k0 += 16) {
        float4 a0 = *(const float4*)(g_hout + (size_t)(m0 + arow) * DM_ + k0 + ak0);
        float4 a1 = *(const float4*)(g_hout + (size_t)(m0 + arow) * DM_ + k0 + ak0 + 4);
        sA[ak0 + 0][arow] = a0.x; sA[ak0 + 1][arow] = a0.y;
        sA[ak0 + 2][arow] = a0.z; sA[ak0 + 3][arow] = a0.w;
        sA[ak0 + 4][arow] = a1.x; sA[ak0 + 5][arow] = a1.y;
        sA[ak0 + 6][arow] = a1.z; sA[ak0 + 7][arow] = a1.w;
        *(float4*)&sB[brow][bc0]     = *(const float4*)(W + (size_t)(k0 + brow) * DM_ + n0 + bc0);
        *(float4*)&sB[brow][bc0 + 4] = *(const float4*)(W + (size_t)(k0 + brow) * DM_ + n0 + bc0 + 4);
        __syncthreads();
#pragma unroll
        for (int k = 0; k < 16; k++) {
            ulonglong2 aA = *(const ulonglong2*)&sA[k][ty * 8];
            ulonglong2 aB = *(const ulonglong2*)&sA[k][ty * 8 + 4];
            float4 b0 = *(const float4*)&sB[k][tx * 8];
            float4 b1 = *(const float4*)&sB[k][tx * 8 + 4];
            float bj[8] = {b0.x, b0.y, b0.z, b0.w, b1.x, b1.y, b1.z, b1.w};
#pragma unroll
            for (int j = 0; j < 8; j++) {
                unsigned long long bb = pk2(bj[j], bj[j]);
                fma2(acc[0][j], aA.x, bb);
                fma2(acc[1][j], aA.y, bb);
                fma2(acc[2][j], aB.x, bb);
                fma2(acc[3][j], aB.y, bb);
            }
        }
        __syncthreads();
    }

#pragma unroll
    for (int p = 0; p < 4; p++) {
        float2 u[8];
#pragma unroll
        for (int j = 0; j < 8; j++) u[j] = upk2(acc[p][j]);
        int nb = n0 + tx * 8;
#pragma unroll
        for (int half = 0; half < 2; half++) {
            int m = m0 + ty * 8 + 2 * p + half;
            float* pp = Cout + (size_t)m * DM_ + nb;
            float4 v0, v1;
            v0.x = (half ? u[0].y : u[0].x) + bias[nb + 0];
            v0.y = (half ? u[1].y : u[1].x) + bias[nb + 1];
            v0.z = (half ? u[2].y : u[2].x) + bias[nb + 2];
            v0.w = (half ? u[3].y : u[3].x) + bias[nb + 3];
            v1.x = (half ? u[4].y : u[4].x) + bias[nb + 4];
            v1.y = (half ? u[5].y : u[5].x) + bias[nb + 5];
            v1.z = (half ? u[6].y : u[6].x) + bias[nb + 6];
            v1.w = (half ? u[7].y : u[7].x) + bias[nb + 7];
            *(float4*)pp = v0;
            *(float4*)(pp + 4) = v1;
        }
    }
}

// ---------------------------------------------------------------------------
extern "C" void kernel_launch(void* const* d_in, const int* in_sizes, int n_in,
                              void* d_out, int out_size)
{
    (void)in_sizes; (void)n_in; (void)out_size;
    const float* x    = (const float*)d_in[0];
    const float* Wqkv = (const float*)d_in[1];
    const float* bqkv = (const float*)d_in[2];
    const float* Wout = (const float*)d_in[3];
    const float* bout = (const float*)d_in[4];
    float* out  = (float*)d_out;
    float* attn = out + OUT_ELEMS_;

    cudaFuncSetAttribute(attn_kernel, cudaFuncAttributeMaxDynamicSharedMemorySize,
                         ATTN_SMEM_BYTES);

    qkv_gemm_kernel<<<dim3(N3_ / 128, (B_ * L_) / 128), 256>>>(x, Wqkv, bqkv);
    attn_kernel<<<dim3(L_ / 128, BH_), 256, ATTN_SMEM_BYTES>>>(attn);
    scale_attn_kernel<<<dim3(BH_ * L_), 256>>>(attn);
    out_gemm_kernel<<<dim3(DM_ / 128, (B_ * L_) / 128), 256>>>(out, Wout, bout);
}

// round 7
// speedup vs baseline: 2.3833x; 1.0277x over previous
#include <cuda_runtime.h>
#include <cstdint>

#define B_ 4
#define L_ 2048
#define H_ 16
#define DH_ 64
#define DM_ 1024
#define N3_ 3072
#define BH_ (B_*H_)
#define OUT_ELEMS_ (B_*L_*DM_)   // 8388608

// Scratch (device globals: allocation-free per harness rules)
__device__ float g_q[BH_*L_*DH_];
__device__ float g_k[BH_*L_*DH_];
__device__ float g_v[BH_*L_*DH_];
__device__ float g_hout[B_*L_*DM_];

// tf32 hi/lo decompositions
__device__ float g_xhi[B_*L_*DM_];
__device__ float g_xlo[B_*L_*DM_];
__device__ float g_wqhi[N3_*DM_];    // [n][k] (transposed W_qkv)
__device__ float g_wqlo[N3_*DM_];
__device__ float g_wohi[DM_*DM_];    // [n][k] (transposed W_out)
__device__ float g_wolo[DM_*DM_];
__device__ float g_hhi[B_*L_*DM_];
__device__ float g_hlo[B_*L_*DM_];

// ---------------------------------------------------------------------------
// Helpers
// ---------------------------------------------------------------------------
__device__ __forceinline__ uint32_t smem_u32(const void* p) {
    uint32_t a;
    asm("{ .reg .u64 t; cvta.to.shared.u64 t, %1; cvt.u32.u64 %0, t; }"
        : "=r"(a) : "l"(p));
    return a;
}
__device__ __forceinline__ void cpa16(uint32_t dst, const float* src) {
    asm volatile("cp.async.cg.shared.global [%0], [%1], 16;" :: "r"(dst), "l"(src));
}
__device__ __forceinline__ float2 tf32split(float a) {
    uint32_t hb;
    asm("cvt.rna.tf32.f32 %0, %1;" : "=r"(hb) : "f"(a));
    float hi = __uint_as_float(hb);
    float lo = a - hi;
    uint32_t lb;
    asm("cvt.rna.tf32.f32 %0, %1;" : "=r"(lb) : "f"(lo));
    return make_float2(hi, __uint_as_float(lb));
}
// m16n8k8 tf32 MMA (baseline PTX, works on compute_103)
__device__ __forceinline__ void mma8(float c[4], const float a[4], const float b[2]) {
    asm volatile(
        "mma.sync.aligned.m16n8k8.row.col.f32.tf32.tf32.f32 "
        "{%0,%1,%2,%3}, {%4,%5,%6,%7}, {%8,%9}, {%0,%1,%2,%3};"
        : "+f"(c[0]), "+f"(c[1]), "+f"(c[2]), "+f"(c[3])
        : "r"(__float_as_uint(a[0])), "r"(__float_as_uint(a[1])),
          "r"(__float_as_uint(a[2])), "r"(__float_as_uint(a[3])),
          "r"(__float_as_uint(b[0])), "r"(__float_as_uint(b[1])));
}

// f32x2 packed FMA (for attn kernel)
__device__ __forceinline__ unsigned long long pk2(float x, float y) {
    unsigned long long r;
    asm("mov.b64 %0, {%1, %2};" : "=l"(r) : "f"(x), "f"(y));
    return r;
}
__device__ __forceinline__ float2 upk2(unsigned long long v) {
    float lo, hi;
    asm("mov.b64 {%0, %1}, %2;" : "=f"(lo), "=f"(hi) : "l"(v));
    return make_float2(lo, hi);
}
__device__ __forceinline__ void fma2(unsigned long long& d,
                                     unsigned long long a,
                                     unsigned long long b) {
    asm("fma.rn.f32x2 %0, %1, %2, %3;" : "=l"(d) : "l"(a), "l"(b), "l"(d));
}

// ---------------------------------------------------------------------------
// Decomposition kernels (plain pointer args; host passes symbol addresses)
// ---------------------------------------------------------------------------
__global__ __launch_bounds__(256) void decomp_kernel(
    const float* __restrict__ src, float* __restrict__ hi, float* __restrict__ lo)
{
    int i = blockIdx.x * 256 + threadIdx.x;
    float4 v = ((const float4*)src)[i];
    float2 sx = tf32split(v.x), sy = tf32split(v.y);
    float2 sz = tf32split(v.z), sw = tf32split(v.w);
    ((float4*)hi)[i] = make_float4(sx.x, sy.x, sz.x, sw.x);
    ((float4*)lo)[i] = make_float4(sx.y, sy.y, sz.y, sw.y);
}

// W[k][n] -> hi/lo [n][k]
__global__ __launch_bounds__(256) void decomp_t_kernel(
    const float* __restrict__ src, float* __restrict__ dhi, float* __restrict__ dlo,
    int K, int N)
{
    __shared__ float t[32][33];
    int k0 = blockIdx.y * 32, n0 = blockIdx.x * 32;
    int r = threadIdx.x >> 3;
    int c4 = (threadIdx.x & 7) * 4;
    float4 v = *(const float4*)(src + (size_t)(k0 + r) * N + n0 + c4);
    t[r][c4 + 0] = v.x; t[r][c4 + 1] = v.y; t[r][c4 + 2] = v.z; t[r][c4 + 3] = v.w;
    __syncthreads();
    float2 s0 = tf32split(t[c4 + 0][r]);
    float2 s1 = tf32split(t[c4 + 1][r]);
    float2 s2 = tf32split(t[c4 + 2][r]);
    float2 s3 = tf32split(t[c4 + 3][r]);
    *(float4*)(dhi + (size_t)(n0 + r) * K + k0 + c4) =
        make_float4(s0.x, s1.x, s2.x, s3.x);
    *(float4*)(dlo + (size_t)(n0 + r) * K + k0 + c4) =
        make_float4(s0.y, s1.y, s2.y, s3.y);
}

// ---------------------------------------------------------------------------
// mma.sync tf32 3x GEMM.  C[128,128] = A[128,1024] @ B^T  (B stored [n][k]).
// MODE 0: out projection  (C -> Cout[m][n] + bias)
// MODE 1: qkv projection  (C + bias scattered into g_q/g_k/g_v)
// 8 warps, warp tile 64x32; 3-stage cp.async pipeline; k-chunk 32.
// smem per stage: 4 arrays [128][36] floats (Ahi, Alo, Bhi, Blo).
// ---------------------------------------------------------------------------
#define ARR_F 4608              // 128*36 floats
#define STAGE_F (4 * ARR_F)     // 18432 floats
#define GEMM_SMEM_BYTES (3 * STAGE_F * 4)   // 221184

template <int MODE>
__global__ __launch_bounds__(256, 1) void gemm_mma_kernel(
    const float* __restrict__ Ahi, const float* __restrict__ Alo,
    const float* __restrict__ Bhi, const float* __restrict__ Blo,
    const float* __restrict__ bias, float* __restrict__ Cout)
{
    extern __shared__ float gsm[];
    const uint32_t sbase = smem_u32(gsm);
    const int tid = threadIdx.x;
    const int wid = tid >> 5;
    const int lane = tid & 31;
    const int grp = lane >> 2;      // 0..7
    const int tg = lane & 3;        // 0..3
    const int n0 = blockIdx.x * 128;
    const int m0 = blockIdx.y * 128;

    const int lrow = tid >> 1;          // 0..127
    const int lg4 = (tid & 1) * 4;      // granule group: floats lg4*4 .. lg4*4+15

    const float* srcA_hi = Ahi + (size_t)(m0 + lrow) * DM_ + lg4 * 4;
    const float* srcA_lo = Alo + (size_t)(m0 + lrow) * DM_ + lg4 * 4;
    const float* srcB_hi = Bhi + (size_t)(n0 + lrow) * DM_ + lg4 * 4;
    const float* srcB_lo = Blo + (size_t)(n0 + lrow) * DM_ + lg4 * 4;

    auto load_chunk = [&](int c) {
        if (c < 32) {
            const int st = c % 3;
            const uint32_t sb = sbase + (st * STAGE_F) * 4;
            const uint32_t dbase = sb + (lrow * 36 + lg4 * 4) * 4;
            const int k0 = c * 32;
#pragma unroll
            for (int j = 0; j < 4; j++) {
                cpa16(dbase + 0 * ARR_F * 4 + j * 16, srcA_hi + k0 + j * 4);
                cpa16(dbase + 1 * ARR_F * 4 + j * 16, srcA_lo + k0 + j * 4);
                cpa16(dbase + 2 * ARR_F * 4 + j * 16, srcB_hi + k0 + j * 4);
                cpa16(dbase + 3 * ARR_F * 4 + j * 16, srcB_lo + k0 + j * 4);
            }
        }
        asm volatile("cp.async.commit_group;" ::: "memory");
    };

    const int wm = wid & 1;         // m-half (64 rows)
    const int wn = wid >> 1;        // n-quarter (32 cols)

    float acc[4][4][4];
#pragma unroll
    for (int mf = 0; mf < 4; mf++)
#pragma unroll
        for (int nf = 0; nf < 4; nf++)
#pragma unroll
            for (int e = 0; e < 4; e++) acc[mf][nf][e] = 0.f;

    load_chunk(0);
    load_chunk(1);

    for (int c = 0; c < 32; c++) {
        asm volatile("cp.async.wait_group 1;" ::: "memory");
        __syncthreads();

        const float* sb = gsm + (c % 3) * STAGE_F;
        const float* sAhi = sb;
        const float* sAlo = sb + ARR_F;
        const float* sBhi = sb + 2 * ARR_F;
        const float* sBlo = sb + 3 * ARR_F;

#pragma unroll
        for (int k8 = 0; k8 < 4; k8++) {
            const int kk = k8 * 8;
            float aH[4][4], aL[4][4];
#pragma unroll
            for (int mf = 0; mf < 4; mf++) {
                int mr = wm * 64 + mf * 16 + grp;
                aH[mf][0] = sAhi[(mr) * 36 + kk + tg];
                aH[mf][1] = sAhi[(mr + 8) * 36 + kk + tg];
                aH[mf][2] = sAhi[(mr) * 36 + kk + tg + 4];
                aH[mf][3] = sAhi[(mr + 8) * 36 + kk + tg + 4];
                aL[mf][0] = sAlo[(mr) * 36 + kk + tg];
                aL[mf][1] = sAlo[(mr + 8) * 36 + kk + tg];
                aL[mf][2] = sAlo[(mr) * 36 + kk + tg + 4];
                aL[mf][3] = sAlo[(mr + 8) * 36 + kk + tg + 4];
            }
            float bH[4][2], bL[4][2];
#pragma unroll
            for (int nf = 0; nf < 4; nf++) {
                int nr = wn * 32 + nf * 8 + grp;
                bH[nf][0] = sBhi[nr * 36 + kk + tg];
                bH[nf][1] = sBhi[nr * 36 + kk + tg + 4];
                bL[nf][0] = sBlo[nr * 36 + kk + tg];
                bL[nf][1] = sBlo[nr * 36 + kk + tg + 4];
            }
#pragma unroll
            for (int mf = 0; mf < 4; mf++)
#pragma unroll
                for (int nf = 0; nf < 4; nf++) {
                    mma8(acc[mf][nf], aH[mf], bH[nf]);
                    mma8(acc[mf][nf], aH[mf], bL[nf]);
                    mma8(acc[mf][nf], aL[mf], bH[nf]);
                }
        }
        __syncthreads();
        load_chunk(c + 2);
    }

    // epilogue: fragment layout -> global (float2 per row-pair element)
#pragma unroll
    for (int mf = 0; mf < 4; mf++) {
#pragma unroll
        for (int nf = 0; nf < 4; nf++) {
            int m = m0 + wm * 64 + mf * 16 + grp;
            int n = n0 + wn * 32 + nf * 8 + tg * 2;
            float b0 = __ldg(bias + n), b1 = __ldg(bias + n + 1);
            float2 v0 = make_float2(acc[mf][nf][0] + b0, acc[mf][nf][1] + b1);
            float2 v1 = make_float2(acc[mf][nf][2] + b0, acc[mf][nf][3] + b1);
            if (MODE == 0) {
                *(float2*)(Cout + (size_t)m * DM_ + n) = v0;
                *(float2*)(Cout + (size_t)(m + 8) * DM_ + n) = v1;
            } else {
                int mat = n >> 10;
                int cc = n & 1023;
                int h = cc >> 6, dd = cc & 63;
                float* dst = (mat == 0) ? g_q : (mat == 1) ? g_k : g_v;
                int bidx = m >> 11;
                int l = m & 2047;
                *(float2*)(dst + (((size_t)(bidx * H_ + h)) * L_ + l) * DH_ + dd) = v0;
                *(float2*)(dst + (((size_t)(bidx * H_ + h)) * L_ + l + 8) * DH_ + dd) = v1;
            }
        }
    }
}

// ---------------------------------------------------------------------------
// Fused attention (R4-proven mainloop): 128 q-rows/CTA, FFMA2 score + AV,
// plus fused in-kernel rescale of this CTA's attn rows (replaces the old
// standalone bandwidth pass; rows are hot in L2 right after being written).
// ---------------------------------------------------------------------------
#define ATTN_SMEM_FLOATS 17280
#define ATTN_SMEM_BYTES  (ATTN_SMEM_FLOATS * 4)

__global__ __launch_bounds__(256, 2) void attn_kernel(float* __restrict__ attn_out)
{
    extern __shared__ float sm[];
    float* sqT = sm;            // [d][row] stride 132
    float* skT = sm + 8448;     // [d][key] stride 68
    float* sv  = sm + 12800;    // [k][dim] stride 68
    float* srow = sm + 17152;   // [128]

    const int tid = threadIdx.x;
    const int bh = blockIdx.y;
    const int q0 = blockIdx.x * 128;
    const float* Q = g_q + (size_t)bh * L_ * DH_;
    const float* K = g_k + (size_t)bh * L_ * DH_;
    const float* V = g_v + (size_t)bh * L_ * DH_;
    float* attn = attn_out + (size_t)bh * L_ * L_;

    {
        int lr = tid >> 1;
        int c0 = (tid & 1) * 32;
#pragma unroll
        for (int w = 0; w < 8; w++) {
            float4 qv = *(const float4*)(Q + (size_t)(q0 + lr) * DH_ + c0 + w * 4);
            sqT[(c0 + w * 4 + 0) * 132 + lr] = qv.x;
            sqT[(c0 + w * 4 + 1) * 132 + lr] = qv.y;
            sqT[(c0 + w * 4 + 2) * 132 + lr] = qv.z;
            sqT[(c0 + w * 4 + 3) * 132 + lr] = qv.w;
        }
    }

    const int ty = tid >> 4;
    const int tx = tid & 15;

    unsigned long long oacc[8][2];
#pragma unroll
    for (int i = 0; i < 8; i++) { oacc[i][0] = 0ull; oacc[i][1] = 0ull; }
    float rsum[8];
#pragma unroll
    for (int i = 0; i < 8; i++) rsum[i] = 0.f;

    const int klr = tid >> 2;
    const int kc  = tid & 3;

    for (int kt = 0; kt < L_ / 64; kt++) {
        const int k0g = kt * 64;
#pragma unroll
        for (int jj = 0; jj < 4; jj++) {
            int d0 = kc * 4 + jj * 16;
            float4 kv = *(const float4*)(K + (size_t)(k0g + klr) * DH_ + d0);
            skT[(d0 + 0) * 68 + klr] = kv.x;
            skT[(d0 + 1) * 68 + klr] = kv.y;
            skT[(d0 + 2) * 68 + klr] = kv.z;
            skT[(d0 + 3) * 68 + klr] = kv.w;
            int vd = kc * 16 + jj * 4;
            float4 vv = *(const float4*)(V + (size_t)(k0g + klr) * DH_ + vd);
            *(float4*)&sv[klr * 68 + vd] = vv;
        }
        __syncthreads();

        unsigned long long s[4][4];
#pragma unroll
        for (int p = 0; p < 4; p++)
#pragma unroll
            for (int j = 0; j < 4; j++) s[p][j] = 0ull;

#pragma unroll 4
        for (int d = 0; d < 64; d++) {
            ulonglong2 qa = *(const ulonglong2*)&sqT[d * 132 + ty * 8];
            ulonglong2 qb = *(const ulonglong2*)&sqT[d * 132 + ty * 8 + 4];
            float4 kf = *(const float4*)&skT[d * 68 + tx * 4];
            float kj[4] = {kf.x, kf.y, kf.z, kf.w};
#pragma unroll
            for (int j = 0; j < 4; j++) {
                unsigned long long kk = pk2(kj[j], kj[j]);
                fma2(s[0][j], qa.x, kk);
                fma2(s[1][j], qa.y, kk);
                fma2(s[2][j], qb.x, kk);
                fma2(s[3][j], qb.y, kk);
            }
        }

        float ev[8][4];
#pragma unroll
        for (int p = 0; p < 4; p++)
#pragma unroll
            for (int j = 0; j < 4; j++) {
                float2 u = upk2(s[p][j]);
                ev[2 * p + 0][j] = __expf(u.x * 0.125f);
                ev[2 * p + 1][j] = __expf(u.y * 0.125f);
            }
#pragma unroll
        for (int i = 0; i < 8; i++) {
            float ls = ev[i][0] + ev[i][1] + ev[i][2] + ev[i][3];
#pragma unroll
            for (int off = 1; off < 16; off <<= 1)
                ls += __shfl_xor_sync(0xffffffffu, ls, off);
            rsum[i] += ls;
            *(float4*)(attn + (size_t)(q0 + ty * 8 + i) * L_ + k0g + tx * 4) =
                make_float4(ev[i][0], ev[i][1], ev[i][2], ev[i][3]);
        }

        __syncthreads();

#pragma unroll 2
        for (int k = 0; k < 64; k += 4) {
            float4 pr[8];
#pragma unroll
            for (int i = 0; i < 8; i++)
                pr[i] = *(const float4*)(attn + (size_t)(q0 + ty * 8 + i) * L_ + k0g + k);
#pragma unroll
            for (int t = 0; t < 4; t++) {
                ulonglong2 vt = *(const ulonglong2*)&sv[(k + t) * 68 + tx * 4];
#pragma unroll
                for (int i = 0; i < 8; i++) {
                    float pv = (t == 0) ? pr[i].x : (t == 1) ? pr[i].y
                             : (t == 2) ? pr[i].z : pr[i].w;
                    unsigned long long pp = pk2(pv, pv);
                    fma2(oacc[i][0], pp, vt.x);
                    fma2(oacc[i][1], pp, vt.y);
                }
            }
        }
        __syncthreads();
    }

    if (tx == 0) {
#pragma unroll
        for (int i = 0; i < 8; i++) srow[ty * 8 + i] = rsum[i];
    }
    __syncthreads();

    const int bidx = bh >> 4;
    const int h = bh & 15;
#pragma unroll
    for (int i = 0; i < 8; i++) {
        float inv = 1.f / srow[ty * 8 + i];
        float2 u0 = upk2(oacc[i][0]);
        float2 u1 = upk2(oacc[i][1]);
        float4 o = make_float4(u0.x * inv, u0.y * inv, u1.x * inv, u1.y * inv);
        *(float4*)(g_hout + ((size_t)(bidx * L_) + q0 + ty * 8 + i) * DM_
                   + h * DH_ + tx * 4) = o;
    }

    // fused rescale of this CTA's 128 attn rows (read mostly L2-hot)
#pragma unroll
    for (int i = 0; i < 8; i++) {
        float inv = 1.f / srow[ty * 8 + i];
        float* rowp = attn + (size_t)(q0 + ty * 8 + i) * L_;
#pragma unroll 4
        for (int j = 0; j < 32; j++) {
            float4* p = (float4*)(rowp + j * 64 + tx * 4);
            float4 v = *p;
            v.x *= inv; v.y *= inv; v.z *= inv; v.w *= inv;
            *p = v;
        }
    }
}

// ---------------------------------------------------------------------------
extern "C" void kernel_launch(void* const* d_in, const int* in_sizes, int n_in,
                              void* d_out, int out_size)
{
    (void)in_sizes; (void)n_in; (void)out_size;
    const float* x    = (const float*)d_in[0];
    const float* Wqkv = (const float*)d_in[1];
    const float* bqkv = (const float*)d_in[2];
    const float* Wout = (const float*)d_in[3];
    const float* bout = (const float*)d_in[4];
    float* out  = (float*)d_out;
    float* attn = out + OUT_ELEMS_;

    static int attr_done = 0;
    if (!attr_done) {
        cudaFuncSetAttribute(attn_kernel,
            cudaFuncAttributeMaxDynamicSharedMemorySize, ATTN_SMEM_BYTES);
        cudaFuncSetAttribute(gemm_mma_kernel<0>,
            cudaFuncAttributeMaxDynamicSharedMemorySize, GEMM_SMEM_BYTES);
        cudaFuncSetAttribute(gemm_mma_kernel<1>,
            cudaFuncAttributeMaxDynamicSharedMemorySize, GEMM_SMEM_BYTES);
        attr_done = 1;
    }

    float *xhi, *xlo, *wqhi, *wqlo, *wohi, *wolo, *hhi, *hlo, *hout;
    cudaGetSymbolAddress((void**)&xhi,  g_xhi);
    cudaGetSymbolAddress((void**)&xlo,  g_xlo);
    cudaGetSymbolAddress((void**)&wqhi, g_wqhi);
    cudaGetSymbolAddress((void**)&wqlo, g_wqlo);
    cudaGetSymbolAddress((void**)&wohi, g_wohi);
    cudaGetSymbolAddress((void**)&wolo, g_wolo);
    cudaGetSymbolAddress((void**)&hhi,  g_hhi);
    cudaGetSymbolAddress((void**)&hlo,  g_hlo);
    cudaGetSymbolAddress((void**)&hout, g_hout);

    // operand decompositions (bandwidth-trivial)
    decomp_kernel<<<OUT_ELEMS_ / 4 / 256, 256>>>(x, xhi, xlo);
    decomp_t_kernel<<<dim3(N3_ / 32, DM_ / 32), 256>>>(Wqkv, wqhi, wqlo, DM_, N3_);
    decomp_t_kernel<<<dim3(DM_ / 32, DM_ / 32), 256>>>(Wout, wohi, wolo, DM_, DM_);

    // QKV projection (mma.sync tf32 3x)
    gemm_mma_kernel<1><<<dim3(N3_ / 128, (B_ * L_) / 128), 256, GEMM_SMEM_BYTES>>>(
        xhi, xlo, wqhi, wqlo, bqkv, nullptr);

    // attention + fused attn rescale
    attn_kernel<<<dim3(L_ / 128, BH_), 256, ATTN_SMEM_BYTES>>>(attn);

    // out projection
    decomp_kernel<<<OUT_ELEMS_ / 4 / 256, 256>>>(hout, hhi, hlo);
    gemm_mma_kernel<0><<<dim3(DM_ / 128, (B_ * L_) / 128), 256, GEMM_SMEM_BYTES>>>(
        hhi, hlo, wohi, wolo, bout, out);
}